// round 2
// baseline (speedup 1.0000x reference)
#include <cuda_runtime.h>
#include <math.h>

#define N_TOK 2048
#define HDIM  512
#define C1    256
#define D2    1024
#define KDIM  256
#define HALFD 128
#define HEADS 4
#define SUBN  512
#define KNN   32

// ---------------- static device scratch (no allocations allowed) ----------------
__device__ float g_h[N_TOK * C1];              // 2 MB
__device__ float g_q[N_TOK * D2];              // 8 MB
__device__ float g_bnpart[2 * KDIM * 128];     // [stat][d][block] transposed partials
__device__ float g_scale[KDIM];
__device__ float g_shift[KDIM];
__device__ float g_s[8u * N_TOK * SUBN];       // 32 MB scores [h*2+p][t][k]
__device__ int   g_idx[N_TOK * HEADS * KNN];   // selected memory rows
__device__ float g_w[N_TOK * HEADS * KNN];     // softmax weights
__device__ float g_partial[N_TOK * HDIM];      // per-token gather result

// pair-sum pruning tables: (i+1)*(j+1) <= 32  -> 119 candidates
__constant__ int c_jm[32]   = {32,16,10,8,6,5,4,4,3,3,2,2,2,2,2,2,
                               1,1,1,1,1,1,1,1,1,1,1,1,1,1,1,1};
__constant__ int c_base[32] = {0,32,48,58,66,72,77,81,85,88,91,93,95,97,99,101,
                               103,104,105,106,107,108,109,110,111,112,113,114,115,116,117,118};

__device__ __forceinline__ float neg_inf() { return __int_as_float(0xff800000u); }

// ---------------- double-buffered fp32 GEMM: C = act(A[MxK] @ B[NxK]^T + bias) --------------
// 64x64 tile, 256 threads, 4x4 micro-tile, BK=16, 2-stage smem pipeline.
template<int K, bool RELU>
__global__ void __launch_bounds__(256) gemm_bias(const float* __restrict__ A,
                                                 const float* __restrict__ B,
                                                 const float* __restrict__ bias,
                                                 float* __restrict__ C, int N)
{
    __shared__ float As[2][16][64];
    __shared__ float Bs[2][16][64];
    const int tid = threadIdx.x;
    const int bm = blockIdx.x * 64, bn = blockIdx.y * 64;
    const int lr = tid >> 2;           // 0..63 row within tile
    const int lc = (tid & 3) << 2;     // 0,4,8,12 k-offset
    const int tx = tid & 15, ty = tid >> 4;
    float acc[4][4] = {};

    const float* Aptr = A + (size_t)(bm + lr) * K + lc;
    const float* Bptr = B + (size_t)(bn + lr) * K + lc;

    float4 av = *(const float4*)(Aptr);
    float4 bv = *(const float4*)(Bptr);
    As[0][lc + 0][lr] = av.x; As[0][lc + 1][lr] = av.y; As[0][lc + 2][lr] = av.z; As[0][lc + 3][lr] = av.w;
    Bs[0][lc + 0][lr] = bv.x; Bs[0][lc + 1][lr] = bv.y; Bs[0][lc + 2][lr] = bv.z; Bs[0][lc + 3][lr] = bv.w;
    __syncthreads();

    int p = 0;
#pragma unroll
    for (int k0 = 0; k0 < K; k0 += 16) {
        // prefetch next k-tile (overlaps with the FFMA chain below)
        const bool more = (k0 + 16) < K;
        if (more) {
            av = *(const float4*)(Aptr + k0 + 16);
            bv = *(const float4*)(Bptr + k0 + 16);
        }
#pragma unroll
        for (int k = 0; k < 16; k++) {
            float4 a = *(const float4*)&As[p][k][ty << 2];
            float4 b = *(const float4*)&Bs[p][k][tx << 2];
            acc[0][0] += a.x * b.x; acc[0][1] += a.x * b.y; acc[0][2] += a.x * b.z; acc[0][3] += a.x * b.w;
            acc[1][0] += a.y * b.x; acc[1][1] += a.y * b.y; acc[1][2] += a.y * b.z; acc[1][3] += a.y * b.w;
            acc[2][0] += a.z * b.x; acc[2][1] += a.z * b.y; acc[2][2] += a.z * b.z; acc[2][3] += a.z * b.w;
            acc[3][0] += a.w * b.x; acc[3][1] += a.w * b.y; acc[3][2] += a.w * b.z; acc[3][3] += a.w * b.w;
        }
        if (more) {
            As[p ^ 1][lc + 0][lr] = av.x; As[p ^ 1][lc + 1][lr] = av.y;
            As[p ^ 1][lc + 2][lr] = av.z; As[p ^ 1][lc + 3][lr] = av.w;
            Bs[p ^ 1][lc + 0][lr] = bv.x; Bs[p ^ 1][lc + 1][lr] = bv.y;
            Bs[p ^ 1][lc + 2][lr] = bv.z; Bs[p ^ 1][lc + 3][lr] = bv.w;
            __syncthreads();
            p ^= 1;
        }
    }
    const int colb = bn + (tx << 2);
    float4 bia = *(const float4*)(bias + colb);
#pragma unroll
    for (int i = 0; i < 4; i++) {
        int row = bm + (ty << 2) + i;
        float4 o;
        o.x = acc[i][0] + bia.x; o.y = acc[i][1] + bia.y;
        o.z = acc[i][2] + bia.z; o.w = acc[i][3] + bia.w;
        if (RELU) {
            o.x = fmaxf(o.x, 0.f); o.y = fmaxf(o.y, 0.f);
            o.z = fmaxf(o.z, 0.f); o.w = fmaxf(o.w, 0.f);
        }
        *(float4*)(C + (size_t)row * N + colb) = o;
    }
}

// ---------------- BN statistics ----------------
__global__ void __launch_bounds__(256) bn_partial()
{
    // block b handles 64 rows of g_q viewed as [8192][256]
    const int b = blockIdx.x, tid = threadIdx.x;
    const float* base = g_q + (size_t)b * 64 * KDIM;
    float s = 0.f, s2 = 0.f;
#pragma unroll 8
    for (int r = 0; r < 64; r++) {
        float v = base[r * KDIM + tid];
        s += v; s2 += v * v;
    }
    // transposed layout: [stat][d][block] so finalize reads contiguously
    g_bnpart[(0 * KDIM + tid) * 128 + b] = s;
    g_bnpart[(1 * KDIM + tid) * 128 + b] = s2;
}

__global__ void __launch_bounds__(256) bn_finalize(const float* __restrict__ gamma,
                                                   const float* __restrict__ beta)
{
    const int d = threadIdx.x;
    const float4* p1 = (const float4*)(g_bnpart + (size_t)(0 * KDIM + d) * 128);
    const float4* p2 = (const float4*)(g_bnpart + (size_t)(1 * KDIM + d) * 128);
    float4 a0 = {0,0,0,0}, a1 = {0,0,0,0}, a2 = {0,0,0,0}, a3 = {0,0,0,0};
#pragma unroll
    for (int i = 0; i < 32; i += 4) {   // 4 independent accumulators -> MLP 4
        float4 v0 = p1[i], v1 = p1[i+1], v2 = p1[i+2], v3 = p1[i+3];
        a0.x += v0.x; a0.y += v0.y; a0.z += v0.z; a0.w += v0.w;
        a1.x += v1.x; a1.y += v1.y; a1.z += v1.z; a1.w += v1.w;
        a2.x += v2.x; a2.y += v2.y; a2.z += v2.z; a2.w += v2.w;
        a3.x += v3.x; a3.y += v3.y; a3.z += v3.z; a3.w += v3.w;
    }
    float s = (a0.x+a0.y+a0.z+a0.w)+(a1.x+a1.y+a1.z+a1.w)
            + (a2.x+a2.y+a2.z+a2.w)+(a3.x+a3.y+a3.z+a3.w);
    a0 = {0,0,0,0}; a1 = {0,0,0,0}; a2 = {0,0,0,0}; a3 = {0,0,0,0};
#pragma unroll
    for (int i = 0; i < 32; i += 4) {
        float4 v0 = p2[i], v1 = p2[i+1], v2 = p2[i+2], v3 = p2[i+3];
        a0.x += v0.x; a0.y += v0.y; a0.z += v0.z; a0.w += v0.w;
        a1.x += v1.x; a1.y += v1.y; a1.z += v1.z; a1.w += v1.w;
        a2.x += v2.x; a2.y += v2.y; a2.z += v2.z; a2.w += v2.w;
        a3.x += v3.x; a3.y += v3.y; a3.z += v3.z; a3.w += v3.w;
    }
    float s2 = (a0.x+a0.y+a0.z+a0.w)+(a1.x+a1.y+a1.z+a1.w)
             + (a2.x+a2.y+a2.z+a2.w)+(a3.x+a3.y+a3.z+a3.w);

    const float inv = 1.0f / 8192.0f;
    float mean = s * inv;
    float var  = s2 * inv - mean * mean;
    float sc = rsqrtf(var + 1e-5f) * gamma[d];
    g_scale[d] = sc;
    g_shift[d] = beta[d] - mean * sc;
}

// ---------------- score GEMM with fused BN normalize (double-buffered) ----------------
__global__ void __launch_bounds__(256) score_gemm(const float* __restrict__ keys)
{
    __shared__ float As[2][16][64];
    __shared__ float Bs[2][16][64];
    const int tid = threadIdx.x;
    const int bm = blockIdx.x * 64, bn = blockIdx.y * 64;
    const int z  = blockIdx.z;               // h*2+p
    const int h  = z >> 1, pz = z & 1;
    const int lr = tid >> 2;
    const int lc = (tid & 3) << 2;
    const int tx = tid & 15, ty = tid >> 4;

    const float* Aptr = g_q + (size_t)(bm + lr) * D2 + h * KDIM + pz * HALFD + lc;
    const float* Bptr = keys + (size_t)z * SUBN * HALFD + (size_t)(bn + lr) * HALFD + lc;
    const int dk0 = pz * HALFD + lc;
    float acc[4][4] = {};

    // stage 0
    {
        float4 av = *(const float4*)(Aptr);
        float4 sc = *(const float4*)(g_scale + dk0);
        float4 sh = *(const float4*)(g_shift + dk0);
        av.x = av.x * sc.x + sh.x; av.y = av.y * sc.y + sh.y;
        av.z = av.z * sc.z + sh.z; av.w = av.w * sc.w + sh.w;
        float4 bv = *(const float4*)(Bptr);
        As[0][lc + 0][lr] = av.x; As[0][lc + 1][lr] = av.y; As[0][lc + 2][lr] = av.z; As[0][lc + 3][lr] = av.w;
        Bs[0][lc + 0][lr] = bv.x; Bs[0][lc + 1][lr] = bv.y; Bs[0][lc + 2][lr] = bv.z; Bs[0][lc + 3][lr] = bv.w;
    }
    __syncthreads();

    int p = 0;
#pragma unroll
    for (int k0 = 0; k0 < HALFD; k0 += 16) {
        const bool more = (k0 + 16) < HALFD;
        float4 av, bv, scv, shv;
        if (more) {
            av = *(const float4*)(Aptr + k0 + 16);
            scv = *(const float4*)(g_scale + dk0 + k0 + 16);
            shv = *(const float4*)(g_shift + dk0 + k0 + 16);
            bv = *(const float4*)(Bptr + k0 + 16);
        }
#pragma unroll
        for (int k = 0; k < 16; k++) {
            float4 a = *(const float4*)&As[p][k][ty << 2];
            float4 b = *(const float4*)&Bs[p][k][tx << 2];
            acc[0][0] += a.x * b.x; acc[0][1] += a.x * b.y; acc[0][2] += a.x * b.z; acc[0][3] += a.x * b.w;
            acc[1][0] += a.y * b.x; acc[1][1] += a.y * b.y; acc[1][2] += a.y * b.z; acc[1][3] += a.y * b.w;
            acc[2][0] += a.z * b.x; acc[2][1] += a.z * b.y; acc[2][2] += a.z * b.z; acc[2][3] += a.z * b.w;
            acc[3][0] += a.w * b.x; acc[3][1] += a.w * b.y; acc[3][2] += a.w * b.z; acc[3][3] += a.w * b.w;
        }
        if (more) {
            av.x = av.x * scv.x + shv.x; av.y = av.y * scv.y + shv.y;
            av.z = av.z * scv.z + shv.z; av.w = av.w * scv.w + shv.w;
            As[p ^ 1][lc + 0][lr] = av.x; As[p ^ 1][lc + 1][lr] = av.y;
            As[p ^ 1][lc + 2][lr] = av.z; As[p ^ 1][lc + 3][lr] = av.w;
            Bs[p ^ 1][lc + 0][lr] = bv.x; Bs[p ^ 1][lc + 1][lr] = bv.y;
            Bs[p ^ 1][lc + 2][lr] = bv.z; Bs[p ^ 1][lc + 3][lr] = bv.w;
            __syncthreads();
            p ^= 1;
        }
    }
    float* S = g_s + (size_t)z * N_TOK * SUBN;
#pragma unroll
    for (int i = 0; i < 4; i++) {
        int row = bm + (ty << 2) + i;
        float4 o = { acc[i][0], acc[i][1], acc[i][2], acc[i][3] };
        *(float4*)(S + (size_t)row * SUBN + bn + (tx << 2)) = o;
    }
}

// ---------------- two-level top-k + softmax ----------------
__global__ void __launch_bounds__(64) topk_kernel()
{
    const int b = blockIdx.x;
    const int t = b >> 2, h = b & 3;
    const int w = threadIdx.x >> 5;          // half index (warp)
    const int lane = threadIdx.x & 31;

    __shared__ float sts[2][32];
    __shared__ int   sti[2][32];
    __shared__ float cv[128];
    __shared__ int   ci[128];

    // phase 1: each warp extracts sorted top-32 of its 512-score row
    {
        const float* row = g_s + ((size_t)(h * 2 + w) * N_TOK + t) * SUBN;
        float v[16];
#pragma unroll
        for (int c = 0; c < 16; c++) v[c] = row[lane + 32 * c];
        float myv = 0.f; int myi = 0;
        for (int it = 0; it < 32; it++) {
            float lm = neg_inf(); int lc2 = 0;
#pragma unroll
            for (int c = 0; c < 16; c++) if (v[c] > lm) { lm = v[c]; lc2 = c; }
            float bv = lm; int bi = lane + 32 * lc2;   // original index, ties -> lower idx
#pragma unroll
            for (int o = 16; o > 0; o >>= 1) {
                float ov = __shfl_xor_sync(0xffffffffu, bv, o);
                int   oi = __shfl_xor_sync(0xffffffffu, bi, o);
                if (ov > bv || (ov == bv && oi < bi)) { bv = ov; bi = oi; }
            }
            if (lane == it) { myv = bv; myi = bi; }
            if (lane == (bi & 31)) {
                int cc = bi >> 5;
#pragma unroll
                for (int c = 0; c < 16; c++) if (c == cc) v[c] = neg_inf();
            }
        }
        sts[w][lane] = myv; sti[w][lane] = myi;
    }
    __syncthreads();

    // phase 2: warp 0 combines pair sums (pruned to 119 candidates), top-32, softmax
    if (w == 0) {
#pragma unroll
        for (int c = 0; c < 4; c++) cv[lane + 32 * c] = neg_inf();
        __syncwarp();
        {
            const int jm = c_jm[lane], base = c_base[lane];
            const float a = sts[0][lane];
            const int  ia = sti[0][lane];
            for (int j = 0; j < jm; j++) {
                cv[base + j] = a + sts[1][j];
                ci[base + j] = ia * SUBN + sti[1][j];
            }
        }
        __syncwarp();
        float v[4];
#pragma unroll
        for (int c = 0; c < 4; c++) v[c] = cv[lane + 32 * c];
        float myv = 0.f; int mys = 0;
        for (int it = 0; it < 32; it++) {
            float lm = neg_inf(); int lc2 = 0;
#pragma unroll
            for (int c = 0; c < 4; c++) if (v[c] > lm) { lm = v[c]; lc2 = c; }
            float bv = lm; int bi = lane + 32 * lc2;   // slot order == lexicographic (i,j)
#pragma unroll
            for (int o = 16; o > 0; o >>= 1) {
                float ov = __shfl_xor_sync(0xffffffffu, bv, o);
                int   oi = __shfl_xor_sync(0xffffffffu, bi, o);
                if (ov > bv || (ov == bv && oi < bi)) { bv = ov; bi = oi; }
            }
            if (lane == it) { myv = bv; mys = bi; }
            if (lane == (bi & 31)) {
                int cc = bi >> 5;
#pragma unroll
                for (int c = 0; c < 4; c++) if (c == cc) v[c] = neg_inf();
            }
        }
        const float mx = __shfl_sync(0xffffffffu, myv, 0);
        float e = expf(myv - mx);
        float sum = e;
#pragma unroll
        for (int o = 16; o > 0; o >>= 1) sum += __shfl_xor_sync(0xffffffffu, sum, o);
        const size_t oo = (size_t)t * (HEADS * KNN) + h * KNN + lane;
        g_idx[oo] = ci[mys];
        g_w[oo]   = e / sum;
    }
}

// ---------------- weighted gather from values table (MLP=4) ----------------
__global__ void __launch_bounds__(128) gather_kernel(const float* __restrict__ values)
{
    const int t = blockIdx.x;
    const int tid = threadIdx.x;
    __shared__ int   sidx[128];
    __shared__ float sw[128];
    sidx[tid] = g_idx[(size_t)t * 128 + tid];
    sw[tid]   = g_w[(size_t)t * 128 + tid];
    __syncthreads();

    const int col = tid << 2;
    float4 a0 = {0,0,0,0}, a1 = {0,0,0,0}, a2 = {0,0,0,0}, a3 = {0,0,0,0};
#pragma unroll
    for (int k = 0; k < 128; k += 4) {
        // 4 independent loads in flight
        const float4 v0 = *(const float4*)(values + (size_t)sidx[k + 0] * HDIM + col);
        const float4 v1 = *(const float4*)(values + (size_t)sidx[k + 1] * HDIM + col);
        const float4 v2 = *(const float4*)(values + (size_t)sidx[k + 2] * HDIM + col);
        const float4 v3 = *(const float4*)(values + (size_t)sidx[k + 3] * HDIM + col);
        const float w0 = sw[k + 0], w1 = sw[k + 1], w2 = sw[k + 2], w3 = sw[k + 3];
        a0.x += w0 * v0.x; a0.y += w0 * v0.y; a0.z += w0 * v0.z; a0.w += w0 * v0.w;
        a1.x += w1 * v1.x; a1.y += w1 * v1.y; a1.z += w1 * v1.z; a1.w += w1 * v1.w;
        a2.x += w2 * v2.x; a2.y += w2 * v2.y; a2.z += w2 * v2.z; a2.w += w2 * v2.w;
        a3.x += w3 * v3.x; a3.y += w3 * v3.y; a3.z += w3 * v3.z; a3.w += w3 * v3.w;
    }
    float4 acc;
    acc.x = (a0.x + a1.x) + (a2.x + a3.x);
    acc.y = (a0.y + a1.y) + (a2.y + a3.y);
    acc.z = (a0.z + a1.z) + (a2.z + a3.z);
    acc.w = (a0.w + a1.w) + (a2.w + a3.w);
    *(float4*)(g_partial + (size_t)t * HDIM + col) = acc;
}

// ---------------- deterministic reduce over sequence ----------------
__global__ void __launch_bounds__(512) reduce_kernel(float* __restrict__ out)
{
    const int e = blockIdx.x * 512 + threadIdx.x;   // 0..16383
    const int bb = e >> 9, c = e & 511;
    float s0 = 0.f, s1 = 0.f, s2 = 0.f, s3 = 0.f;
#pragma unroll
    for (int l = 0; l < 64; l += 4) {
        s0 += g_partial[(size_t)((bb << 6) + l + 0) * HDIM + c];
        s1 += g_partial[(size_t)((bb << 6) + l + 1) * HDIM + c];
        s2 += g_partial[(size_t)((bb << 6) + l + 2) * HDIM + c];
        s3 += g_partial[(size_t)((bb << 6) + l + 3) * HDIM + c];
    }
    out[e] = (s0 + s1) + (s2 + s3);
}

// ---------------- launch ----------------
extern "C" void kernel_launch(void* const* d_in, const int* in_sizes, int n_in,
                              void* d_out, int out_size)
{
    (void)in_sizes; (void)n_in; (void)out_size;
    const float* x        = (const float*)d_in[0];
    const float* w1       = (const float*)d_in[1];
    const float* b1       = (const float*)d_in[2];
    const float* w2       = (const float*)d_in[3];
    const float* b2       = (const float*)d_in[4];
    const float* bn_gamma = (const float*)d_in[5];
    const float* bn_beta  = (const float*)d_in[6];
    const float* keys     = (const float*)d_in[7];
    const float* values   = (const float*)d_in[8];
    float* out = (float*)d_out;

    float *d_h, *d_q;
    cudaGetSymbolAddress((void**)&d_h, g_h);
    cudaGetSymbolAddress((void**)&d_q, g_q);

    // 1) h = relu(x @ w1^T + b1)   [2048 x 256]
    gemm_bias<HDIM, true><<<dim3(N_TOK / 64, C1 / 64), 256>>>(x, w1, b1, d_h, C1);
    // 2) q = h @ w2^T + b2         [2048 x 1024]
    gemm_bias<C1, false><<<dim3(N_TOK / 64, D2 / 64), 256>>>(d_h, w2, b2, d_q, D2);
    // 3) BN stats
    bn_partial<<<128, 256>>>();
    bn_finalize<<<1, 256>>>(bn_gamma, bn_beta);
    // 4) scores (fused normalize) [8][2048][512]
    score_gemm<<<dim3(N_TOK / 64, SUBN / 64, 8), 256>>>(keys);
    // 5) two-level top-k + softmax
    topk_kernel<<<N_TOK * HEADS, 64>>>();
    // 6) weighted gather
    gather_kernel<<<N_TOK, 128>>>(values);
    // 7) sum over sequence
    reduce_kernel<<<32, 512>>>(out);
}

// round 3
// speedup vs baseline: 1.1200x; 1.1200x over previous
#include <cuda_runtime.h>
#include <math.h>

#define N_TOK 2048
#define HDIM  512
#define C1    256
#define D2    1024
#define KDIM  256
#define HALFD 128
#define HEADS 4
#define SUBN  512
#define KNN   32

// ---------------- static device scratch (no allocations allowed) ----------------
__device__ float g_h[N_TOK * C1];                 // 2 MB
__device__ float g_c1part[4 * N_TOK * C1];        // 8 MB split-K partials for gemm1
__device__ float g_q[N_TOK * D2];                 // 8 MB
__device__ float g_bnpart[2 * KDIM * 128];        // [stat][d][block]
__device__ float g_scale[KDIM];
__device__ float g_shift[KDIM];
__device__ float g_s[8u * N_TOK * SUBN];          // 32 MB scores [z][t][k]
__device__ int   g_idx[N_TOK * HEADS * KNN];
__device__ float g_w[N_TOK * HEADS * KNN];
__device__ float g_partial[N_TOK * HDIM];         // per-token gather result

// pair-sum pruning tables: (i+1)*(j+1) <= 32  -> 119 candidates
__constant__ int c_jm[32]   = {32,16,10,8,6,5,4,4,3,3,2,2,2,2,2,2,
                               1,1,1,1,1,1,1,1,1,1,1,1,1,1,1,1};
__constant__ int c_base[32] = {0,32,48,58,66,72,77,81,85,88,91,93,95,97,99,101,
                               103,104,105,106,107,108,109,110,111,112,113,114,115,116,117,118};

__device__ __forceinline__ float neg_inf() { return __int_as_float(0xff800000u); }

// =====================================================================================
// 128x128 tile SGEMM, 256 threads, 8x8 microtile, BK=16. C = act(A @ B^T [+ bias]).
//   A: rows M, row-stride LDA (plus per-z column offset aZ)
//   B: rows N, row-stride LDB (plus per-z offset bZ)
//   C: row-stride ldc (plus per-z offset cZ)
//   NORM: apply g_scale/g_shift along k (BN-normalized A) for the score GEMM.
// Warp tile 64x32, lane grid 8x4, per-lane 8x8. b-frag smem reads are broadcast
// conflict-free; a-frag 2-way. FFMA:LDS issue ratio 32:1 -> FMA-pipe bound.
// =====================================================================================
template<int K, int LDA, int LDB, bool RELU, bool HASBIAS, bool NORM>
__global__ void __launch_bounds__(256) sgemm128(const float* __restrict__ A,
                                                const float* __restrict__ B,
                                                const float* __restrict__ bias,
                                                float* __restrict__ C,
                                                int ldc, int aZ, int bZ, size_t cZ)
{
    __shared__ float As[16][132];
    __shared__ float Bs[16][132];
    const int tid = threadIdx.x;
    const int z = blockIdx.z;
    const int bm = blockIdx.x * 128, bn = blockIdx.y * 128;
    A += (size_t)z * aZ;           // column offset within row (score: z*128; splitK: z*128)
    B += (size_t)z * bZ;
    C += (size_t)z * cZ;

    const int lrow = tid >> 1;               // 0..127
    const int lkc  = (tid & 1) << 3;         // 0 or 8
    const float* Aptr = A + (size_t)(bm + lrow) * LDA + lkc;
    const float* Bptr = B + (size_t)(bn + lrow) * LDB + lkc;

    const int w = tid >> 5, lane = tid & 31;
    const int row0 = ((w & 1) << 6) + ((lane & 7) << 3);   // 0..120
    const int col0 = ((w >> 1) << 5) + ((lane >> 3) << 3); // 0..120

    float acc[8][8] = {};
    float4 a0, a1, b0, b1;

    // ---- load k-tile 0 ----
    a0 = *(const float4*)(Aptr);     a1 = *(const float4*)(Aptr + 4);
    b0 = *(const float4*)(Bptr);     b1 = *(const float4*)(Bptr + 4);
    if (NORM) {
        const int dk = ((z & 1) << 7) + lkc;
        float4 sc0 = *(const float4*)(g_scale + dk), sh0 = *(const float4*)(g_shift + dk);
        float4 sc1 = *(const float4*)(g_scale + dk + 4), sh1 = *(const float4*)(g_shift + dk + 4);
        a0.x = fmaf(a0.x, sc0.x, sh0.x); a0.y = fmaf(a0.y, sc0.y, sh0.y);
        a0.z = fmaf(a0.z, sc0.z, sh0.z); a0.w = fmaf(a0.w, sc0.w, sh0.w);
        a1.x = fmaf(a1.x, sc1.x, sh1.x); a1.y = fmaf(a1.y, sc1.y, sh1.y);
        a1.z = fmaf(a1.z, sc1.z, sh1.z); a1.w = fmaf(a1.w, sc1.w, sh1.w);
    }
    As[lkc+0][lrow]=a0.x; As[lkc+1][lrow]=a0.y; As[lkc+2][lrow]=a0.z; As[lkc+3][lrow]=a0.w;
    As[lkc+4][lrow]=a1.x; As[lkc+5][lrow]=a1.y; As[lkc+6][lrow]=a1.z; As[lkc+7][lrow]=a1.w;
    Bs[lkc+0][lrow]=b0.x; Bs[lkc+1][lrow]=b0.y; Bs[lkc+2][lrow]=b0.z; Bs[lkc+3][lrow]=b0.w;
    Bs[lkc+4][lrow]=b1.x; Bs[lkc+5][lrow]=b1.y; Bs[lkc+6][lrow]=b1.z; Bs[lkc+7][lrow]=b1.w;
    __syncthreads();

#pragma unroll 1
    for (int kb = 1; kb <= K / 16; kb++) {
        const bool more = kb < K / 16;
        if (more) {
            const int k0 = kb * 16;
            a0 = *(const float4*)(Aptr + k0);     a1 = *(const float4*)(Aptr + k0 + 4);
            b0 = *(const float4*)(Bptr + k0);     b1 = *(const float4*)(Bptr + k0 + 4);
            if (NORM) {
                const int dk = ((z & 1) << 7) + lkc + k0;
                float4 sc0 = *(const float4*)(g_scale + dk), sh0 = *(const float4*)(g_shift + dk);
                float4 sc1 = *(const float4*)(g_scale + dk + 4), sh1 = *(const float4*)(g_shift + dk + 4);
                a0.x = fmaf(a0.x, sc0.x, sh0.x); a0.y = fmaf(a0.y, sc0.y, sh0.y);
                a0.z = fmaf(a0.z, sc0.z, sh0.z); a0.w = fmaf(a0.w, sc0.w, sh0.w);
                a1.x = fmaf(a1.x, sc1.x, sh1.x); a1.y = fmaf(a1.y, sc1.y, sh1.y);
                a1.z = fmaf(a1.z, sc1.z, sh1.z); a1.w = fmaf(a1.w, sc1.w, sh1.w);
            }
        }
#pragma unroll
        for (int k = 0; k < 16; k++) {
            float4 af0 = *(const float4*)&As[k][row0];
            float4 af1 = *(const float4*)&As[k][row0 + 4];
            float4 bf0 = *(const float4*)&Bs[k][col0];
            float4 bf1 = *(const float4*)&Bs[k][col0 + 4];
            const float ar[8] = {af0.x,af0.y,af0.z,af0.w,af1.x,af1.y,af1.z,af1.w};
            const float br[8] = {bf0.x,bf0.y,bf0.z,bf0.w,bf1.x,bf1.y,bf1.z,bf1.w};
#pragma unroll
            for (int i = 0; i < 8; i++)
#pragma unroll
                for (int j = 0; j < 8; j++)
                    acc[i][j] = fmaf(ar[i], br[j], acc[i][j]);
        }
        if (more) {
            __syncthreads();
            As[lkc+0][lrow]=a0.x; As[lkc+1][lrow]=a0.y; As[lkc+2][lrow]=a0.z; As[lkc+3][lrow]=a0.w;
            As[lkc+4][lrow]=a1.x; As[lkc+5][lrow]=a1.y; As[lkc+6][lrow]=a1.z; As[lkc+7][lrow]=a1.w;
            Bs[lkc+0][lrow]=b0.x; Bs[lkc+1][lrow]=b0.y; Bs[lkc+2][lrow]=b0.z; Bs[lkc+3][lrow]=b0.w;
            Bs[lkc+4][lrow]=b1.x; Bs[lkc+5][lrow]=b1.y; Bs[lkc+6][lrow]=b1.z; Bs[lkc+7][lrow]=b1.w;
            __syncthreads();
        }
    }

    float4 bb0 = {0,0,0,0}, bb1 = {0,0,0,0};
    if (HASBIAS) {
        bb0 = *(const float4*)(bias + bn + col0);
        bb1 = *(const float4*)(bias + bn + col0 + 4);
    }
#pragma unroll
    for (int i = 0; i < 8; i++) {
        const int r = bm + row0 + i;
        float4 o0 = { acc[i][0] + bb0.x, acc[i][1] + bb0.y, acc[i][2] + bb0.z, acc[i][3] + bb0.w };
        float4 o1 = { acc[i][4] + bb1.x, acc[i][5] + bb1.y, acc[i][6] + bb1.z, acc[i][7] + bb1.w };
        if (RELU) {
            o0.x = fmaxf(o0.x, 0.f); o0.y = fmaxf(o0.y, 0.f); o0.z = fmaxf(o0.z, 0.f); o0.w = fmaxf(o0.w, 0.f);
            o1.x = fmaxf(o1.x, 0.f); o1.y = fmaxf(o1.y, 0.f); o1.z = fmaxf(o1.z, 0.f); o1.w = fmaxf(o1.w, 0.f);
        }
        *(float4*)(C + (size_t)r * ldc + bn + col0)     = o0;
        *(float4*)(C + (size_t)r * ldc + bn + col0 + 4) = o1;
    }
}

// ---------------- split-K combine for gemm1: g_h = relu(sum4 + b1) ----------------
__global__ void __launch_bounds__(256) combine_relu(const float* __restrict__ b1)
{
    const int i = blockIdx.x * 256 + threadIdx.x;      // float4 id, 131072 total
    const int c4 = (i & 63) << 2;
    const size_t off = (size_t)i;                      // float4 index into 2048x256
    const float4* p = (const float4*)g_c1part;
    const size_t stride = (size_t)N_TOK * C1 / 4;
    float4 v0 = p[off], v1 = p[off + stride], v2 = p[off + 2*stride], v3 = p[off + 3*stride];
    float4 bb = *(const float4*)(b1 + c4);
    float4 o;
    o.x = fmaxf((v0.x + v1.x) + (v2.x + v3.x) + bb.x, 0.f);
    o.y = fmaxf((v0.y + v1.y) + (v2.y + v3.y) + bb.y, 0.f);
    o.z = fmaxf((v0.z + v1.z) + (v2.z + v3.z) + bb.z, 0.f);
    o.w = fmaxf((v0.w + v1.w) + (v2.w + v3.w) + bb.w, 0.f);
    ((float4*)g_h)[off] = o;
}

// ---------------- BN statistics ----------------
__global__ void __launch_bounds__(256) bn_partial()
{
    const int b = blockIdx.x, tid = threadIdx.x;
    const float* base = g_q + (size_t)b * 64 * KDIM;
    float s = 0.f, s2 = 0.f;
#pragma unroll 8
    for (int r = 0; r < 64; r++) {
        float v = base[r * KDIM + tid];
        s += v; s2 += v * v;
    }
    g_bnpart[(size_t)tid * 128 + b]          = s;   // stat0
    g_bnpart[(size_t)(KDIM + tid) * 128 + b] = s2;  // stat1
}

__global__ void __launch_bounds__(128) bn_finalize(const float* __restrict__ gamma,
                                                   const float* __restrict__ beta)
{
    const int d = blockIdx.x, t = threadIdx.x;
    float s  = g_bnpart[(size_t)d * 128 + t];
    float s2 = g_bnpart[(size_t)(KDIM + d) * 128 + t];
#pragma unroll
    for (int o = 16; o > 0; o >>= 1) {
        s  += __shfl_xor_sync(0xffffffffu, s, o);
        s2 += __shfl_xor_sync(0xffffffffu, s2, o);
    }
    __shared__ float r1[4], r2[4];
    if ((t & 31) == 0) { r1[t >> 5] = s; r2[t >> 5] = s2; }
    __syncthreads();
    if (t == 0) {
        s  = (r1[0] + r1[1]) + (r1[2] + r1[3]);
        s2 = (r2[0] + r2[1]) + (r2[2] + r2[3]);
        const float inv = 1.0f / 8192.0f;
        float mean = s * inv;
        float var  = s2 * inv - mean * mean;
        float sc = rsqrtf(var + 1e-5f) * gamma[d];
        g_scale[d] = sc;
        g_shift[d] = beta[d] - mean * sc;
    }
}

// ---------------- two-level top-k + softmax ----------------
__global__ void __launch_bounds__(64) topk_kernel()
{
    const int b = blockIdx.x;
    const int t = b >> 2, h = b & 3;
    const int w = threadIdx.x >> 5;
    const int lane = threadIdx.x & 31;

    __shared__ float sts[2][32];
    __shared__ int   sti[2][32];
    __shared__ float cv[128];
    __shared__ int   ci[128];

    {
        const float* row = g_s + ((size_t)(h * 2 + w) * N_TOK + t) * SUBN;
        float v[16];
#pragma unroll
        for (int c = 0; c < 16; c++) v[c] = row[lane + 32 * c];
        float myv = 0.f; int myi = 0;
        for (int it = 0; it < 32; it++) {
            float lm = neg_inf(); int lc2 = 0;
#pragma unroll
            for (int c = 0; c < 16; c++) if (v[c] > lm) { lm = v[c]; lc2 = c; }
            float bv = lm; int bi = lane + 32 * lc2;
#pragma unroll
            for (int o = 16; o > 0; o >>= 1) {
                float ov = __shfl_xor_sync(0xffffffffu, bv, o);
                int   oi = __shfl_xor_sync(0xffffffffu, bi, o);
                if (ov > bv || (ov == bv && oi < bi)) { bv = ov; bi = oi; }
            }
            if (lane == it) { myv = bv; myi = bi; }
            if (lane == (bi & 31)) {
                int cc = bi >> 5;
#pragma unroll
                for (int c = 0; c < 16; c++) if (c == cc) v[c] = neg_inf();
            }
        }
        sts[w][lane] = myv; sti[w][lane] = myi;
    }
    __syncthreads();

    if (w == 0) {
#pragma unroll
        for (int c = 0; c < 4; c++) cv[lane + 32 * c] = neg_inf();
        __syncwarp();
        {
            const int jm = c_jm[lane], base = c_base[lane];
            const float a = sts[0][lane];
            const int  ia = sti[0][lane];
            for (int j = 0; j < jm; j++) {
                cv[base + j] = a + sts[1][j];
                ci[base + j] = ia * SUBN + sti[1][j];
            }
        }
        __syncwarp();
        float v[4];
#pragma unroll
        for (int c = 0; c < 4; c++) v[c] = cv[lane + 32 * c];
        float myv = 0.f; int mys = 0;
        for (int it = 0; it < 32; it++) {
            float lm = neg_inf(); int lc2 = 0;
#pragma unroll
            for (int c = 0; c < 4; c++) if (v[c] > lm) { lm = v[c]; lc2 = c; }
            float bv = lm; int bi = lane + 32 * lc2;
#pragma unroll
            for (int o = 16; o > 0; o >>= 1) {
                float ov = __shfl_xor_sync(0xffffffffu, bv, o);
                int   oi = __shfl_xor_sync(0xffffffffu, bi, o);
                if (ov > bv || (ov == bv && oi < bi)) { bv = ov; bi = oi; }
            }
            if (lane == it) { myv = bv; mys = bi; }
            if (lane == (bi & 31)) {
                int cc = bi >> 5;
#pragma unroll
                for (int c = 0; c < 4; c++) if (c == cc) v[c] = neg_inf();
            }
        }
        const float mx = __shfl_sync(0xffffffffu, myv, 0);
        float e = expf(myv - mx);
        float sum = e;
#pragma unroll
        for (int o = 16; o > 0; o >>= 1) sum += __shfl_xor_sync(0xffffffffu, sum, o);
        const size_t oo = (size_t)t * (HEADS * KNN) + h * KNN + lane;
        g_idx[oo] = ci[mys];
        g_w[oo]   = e / sum;
    }
}

// ---------------- weighted gather from values table (MLP=4) ----------------
__global__ void __launch_bounds__(128) gather_kernel(const float* __restrict__ values)
{
    const int t = blockIdx.x;
    const int tid = threadIdx.x;
    __shared__ int   sidx[128];
    __shared__ float sw[128];
    sidx[tid] = g_idx[(size_t)t * 128 + tid];
    sw[tid]   = g_w[(size_t)t * 128 + tid];
    __syncthreads();

    const int col = tid << 2;
    float4 a0 = {0,0,0,0}, a1 = {0,0,0,0}, a2 = {0,0,0,0}, a3 = {0,0,0,0};
#pragma unroll
    for (int k = 0; k < 128; k += 4) {
        const float4 v0 = *(const float4*)(values + (size_t)sidx[k + 0] * HDIM + col);
        const float4 v1 = *(const float4*)(values + (size_t)sidx[k + 1] * HDIM + col);
        const float4 v2 = *(const float4*)(values + (size_t)sidx[k + 2] * HDIM + col);
        const float4 v3 = *(const float4*)(values + (size_t)sidx[k + 3] * HDIM + col);
        const float w0 = sw[k + 0], w1 = sw[k + 1], w2 = sw[k + 2], w3 = sw[k + 3];
        a0.x += w0 * v0.x; a0.y += w0 * v0.y; a0.z += w0 * v0.z; a0.w += w0 * v0.w;
        a1.x += w1 * v1.x; a1.y += w1 * v1.y; a1.z += w1 * v1.z; a1.w += w1 * v1.w;
        a2.x += w2 * v2.x; a2.y += w2 * v2.y; a2.z += w2 * v2.z; a2.w += w2 * v2.w;
        a3.x += w3 * v3.x; a3.y += w3 * v3.y; a3.z += w3 * v3.z; a3.w += w3 * v3.w;
    }
    float4 acc;
    acc.x = (a0.x + a1.x) + (a2.x + a3.x);
    acc.y = (a0.y + a1.y) + (a2.y + a3.y);
    acc.z = (a0.z + a1.z) + (a2.z + a3.z);
    acc.w = (a0.w + a1.w) + (a2.w + a3.w);
    *(float4*)(g_partial + (size_t)t * HDIM + col) = acc;
}

// ---------------- deterministic reduce over sequence ----------------
__global__ void __launch_bounds__(512) reduce_kernel(float* __restrict__ out)
{
    const int e = blockIdx.x * 512 + threadIdx.x;   // 0..16383
    const int bb = e >> 9, c = e & 511;
    float s0 = 0.f, s1 = 0.f, s2 = 0.f, s3 = 0.f;
#pragma unroll
    for (int l = 0; l < 64; l += 4) {
        s0 += g_partial[(size_t)((bb << 6) + l + 0) * HDIM + c];
        s1 += g_partial[(size_t)((bb << 6) + l + 1) * HDIM + c];
        s2 += g_partial[(size_t)((bb << 6) + l + 2) * HDIM + c];
        s3 += g_partial[(size_t)((bb << 6) + l + 3) * HDIM + c];
    }
    out[e] = (s0 + s1) + (s2 + s3);
}

// ---------------- launch ----------------
extern "C" void kernel_launch(void* const* d_in, const int* in_sizes, int n_in,
                              void* d_out, int out_size)
{
    (void)in_sizes; (void)n_in; (void)out_size;
    const float* x        = (const float*)d_in[0];
    const float* w1       = (const float*)d_in[1];
    const float* b1       = (const float*)d_in[2];
    const float* w2       = (const float*)d_in[3];
    const float* b2       = (const float*)d_in[4];
    const float* bn_gamma = (const float*)d_in[5];
    const float* bn_beta  = (const float*)d_in[6];
    const float* keys     = (const float*)d_in[7];
    const float* values   = (const float*)d_in[8];
    float* out = (float*)d_out;

    float *d_h, *d_q, *d_c1, *d_s;
    cudaGetSymbolAddress((void**)&d_h, g_h);
    cudaGetSymbolAddress((void**)&d_q, g_q);
    cudaGetSymbolAddress((void**)&d_c1, g_c1part);
    cudaGetSymbolAddress((void**)&d_s, g_s);

    // 1) gemm1 split-K=4: partials [4][2048x256]  (K chunk 128, column offsets z*128)
    sgemm128<128, HDIM, HDIM, false, false, false>
        <<<dim3(16, 2, 4), 256>>>(x, w1, nullptr, d_c1, C1, 128, 128, (size_t)N_TOK * C1);
    // 1b) combine + bias + relu -> g_h
    combine_relu<<<512, 256>>>(b1);
    // 2) q = h @ w2^T + b2   [2048 x 1024]
    sgemm128<C1, C1, C1, false, true, false>
        <<<dim3(16, 8, 1), 256>>>(d_h, w2, b2, d_q, D2, 0, 0, 0);
    // 3) BN stats
    bn_partial<<<128, 256>>>();
    bn_finalize<<<KDIM, 128>>>(bn_gamma, bn_beta);
    // 4) scores with fused BN normalize  [8][2048][512]
    sgemm128<HALFD, D2, HALFD, false, false, true>
        <<<dim3(16, 4, 8), 256>>>(d_q, keys, nullptr, d_s, SUBN,
                                  128, SUBN * HALFD, (size_t)N_TOK * SUBN);
    // 5) two-level top-k + softmax
    topk_kernel<<<N_TOK * HEADS, 64>>>();
    // 6) weighted gather
    gather_kernel<<<N_TOK, 128>>>(values);
    // 7) sum over sequence
    reduce_kernel<<<32, 512>>>(out);
}

// round 4
// speedup vs baseline: 1.1211x; 1.0009x over previous
#include <cuda_runtime.h>
#include <math.h>

#define N_TOK 2048
#define HDIM  512
#define C1    256
#define D2    1024
#define KDIM  256
#define HALFD 128
#define HEADS 4
#define SUBN  512
#define KNN   32

typedef unsigned long long u64t;

// packed fp32x2 FMA (sm_100+): d.lo += a.lo*b.lo, d.hi += a.hi*b.hi
__device__ __forceinline__ u64t pack2(float lo, float hi) {
    u64t r; asm("mov.b64 %0, {%1, %2};" : "=l"(r) : "f"(lo), "f"(hi)); return r;
}
__device__ __forceinline__ void ffma2(u64t& d, u64t a, u64t b) {
    asm("fma.rn.f32x2 %0, %1, %2, %0;" : "+l"(d) : "l"(a), "l"(b));
}
__device__ __forceinline__ void unpack2(u64t v, float& lo, float& hi) {
    asm("mov.b64 {%0, %1}, %2;" : "=f"(lo), "=f"(hi) : "l"(v));
}

// ---------------- static device scratch (no allocations allowed) ----------------
__device__ float g_h[N_TOK * C1];                 // 2 MB
__device__ float g_c1part[4 * N_TOK * C1];        // 8 MB split-K partials for gemm1
__device__ float g_q[N_TOK * D2];                 // 8 MB
__device__ float g_bnpart[2 * KDIM * 256];        // [stat][d][block]
__device__ float g_scale[KDIM];
__device__ float g_shift[KDIM];
__device__ float g_s[8u * N_TOK * SUBN];          // 32 MB scores [z][t][k]
__device__ int   g_idx[N_TOK * HEADS * KNN];
__device__ float g_w[N_TOK * HEADS * KNN];
__device__ float g_partial[N_TOK * HDIM];         // per-token gather result

// pair-sum pruning tables: (i+1)*(j+1) <= 32  -> 119 candidates
__constant__ int c_jm[32]   = {32,16,10,8,6,5,4,4,3,3,2,2,2,2,2,2,
                               1,1,1,1,1,1,1,1,1,1,1,1,1,1,1,1};
__constant__ int c_base[32] = {0,32,48,58,66,72,77,81,85,88,91,93,95,97,99,101,
                               103,104,105,106,107,108,109,110,111,112,113,114,115,116,117,118};

__device__ __forceinline__ float neg_inf() { return __int_as_float(0xff800000u); }

// =====================================================================================
// 128x128 tile SGEMM, 256 threads, 8x8 microtile via packed f32x2 FFMA2, BK=16.
// acc2[j][p] holds rows {2p,2p+1} of column j.
// Inner k-step: 4x LDS.128 + 8 packs + 32 FFMA2  (vs 64 scalar FFMA).
// =====================================================================================
template<int K, int LDA, int LDB, bool RELU, bool HASBIAS, bool NORM>
__global__ void __launch_bounds__(256) sgemm128(const float* __restrict__ A,
                                                const float* __restrict__ B,
                                                const float* __restrict__ bias,
                                                float* __restrict__ C,
                                                int ldc, int aZ, int bZ, size_t cZ)
{
    __shared__ float As[16][132];
    __shared__ float Bs[16][132];
    const int tid = threadIdx.x;
    const int z = blockIdx.z;
    const int bm = blockIdx.x * 128, bn = blockIdx.y * 128;
    A += (size_t)z * aZ;
    B += (size_t)z * bZ;
    C += (size_t)z * cZ;

    const int lrow = tid >> 1;               // 0..127
    const int lkc  = (tid & 1) << 3;         // 0 or 8
    const float* Aptr = A + (size_t)(bm + lrow) * LDA + lkc;
    const float* Bptr = B + (size_t)(bn + lrow) * LDB + lkc;

    const int w = tid >> 5, lane = tid & 31;
    const int row0 = ((w & 1) << 6) + ((lane & 7) << 3);   // 0..120
    const int col0 = ((w >> 1) << 5) + ((lane >> 3) << 3); // 0..120

    u64t acc2[8][4];
#pragma unroll
    for (int j = 0; j < 8; j++)
#pragma unroll
        for (int p = 0; p < 4; p++) acc2[j][p] = 0ull;

    float4 a0, a1, b0, b1;

    // ---- load k-tile 0 ----
    a0 = *(const float4*)(Aptr);     a1 = *(const float4*)(Aptr + 4);
    b0 = *(const float4*)(Bptr);     b1 = *(const float4*)(Bptr + 4);
    if (NORM) {
        const int dk = ((z & 1) << 7) + lkc;
        float4 sc0 = *(const float4*)(g_scale + dk), sh0 = *(const float4*)(g_shift + dk);
        float4 sc1 = *(const float4*)(g_scale + dk + 4), sh1 = *(const float4*)(g_shift + dk + 4);
        a0.x = fmaf(a0.x, sc0.x, sh0.x); a0.y = fmaf(a0.y, sc0.y, sh0.y);
        a0.z = fmaf(a0.z, sc0.z, sh0.z); a0.w = fmaf(a0.w, sc0.w, sh0.w);
        a1.x = fmaf(a1.x, sc1.x, sh1.x); a1.y = fmaf(a1.y, sc1.y, sh1.y);
        a1.z = fmaf(a1.z, sc1.z, sh1.z); a1.w = fmaf(a1.w, sc1.w, sh1.w);
    }
    As[lkc+0][lrow]=a0.x; As[lkc+1][lrow]=a0.y; As[lkc+2][lrow]=a0.z; As[lkc+3][lrow]=a0.w;
    As[lkc+4][lrow]=a1.x; As[lkc+5][lrow]=a1.y; As[lkc+6][lrow]=a1.z; As[lkc+7][lrow]=a1.w;
    Bs[lkc+0][lrow]=b0.x; Bs[lkc+1][lrow]=b0.y; Bs[lkc+2][lrow]=b0.z; Bs[lkc+3][lrow]=b0.w;
    Bs[lkc+4][lrow]=b1.x; Bs[lkc+5][lrow]=b1.y; Bs[lkc+6][lrow]=b1.z; Bs[lkc+7][lrow]=b1.w;
    __syncthreads();

#pragma unroll 1
    for (int kb = 1; kb <= K / 16; kb++) {
        const bool more = kb < K / 16;
        if (more) {
            const int k0 = kb * 16;
            a0 = *(const float4*)(Aptr + k0);     a1 = *(const float4*)(Aptr + k0 + 4);
            b0 = *(const float4*)(Bptr + k0);     b1 = *(const float4*)(Bptr + k0 + 4);
            if (NORM) {
                const int dk = ((z & 1) << 7) + lkc + k0;
                float4 sc0 = *(const float4*)(g_scale + dk), sh0 = *(const float4*)(g_shift + dk);
                float4 sc1 = *(const float4*)(g_scale + dk + 4), sh1 = *(const float4*)(g_shift + dk + 4);
                a0.x = fmaf(a0.x, sc0.x, sh0.x); a0.y = fmaf(a0.y, sc0.y, sh0.y);
                a0.z = fmaf(a0.z, sc0.z, sh0.z); a0.w = fmaf(a0.w, sc0.w, sh0.w);
                a1.x = fmaf(a1.x, sc1.x, sh1.x); a1.y = fmaf(a1.y, sc1.y, sh1.y);
                a1.z = fmaf(a1.z, sc1.z, sh1.z); a1.w = fmaf(a1.w, sc1.w, sh1.w);
            }
        }
#pragma unroll
        for (int k = 0; k < 16; k++) {
            // a fragment as 4 packed row-pairs (smem is 16B-aligned here)
            const u64t* ap0 = (const u64t*)&As[k][row0];
            const u64t* ap1 = (const u64t*)&As[k][row0 + 4];
            const u64t apair0 = ap0[0], apair1 = ap0[1], apair2 = ap1[0], apair3 = ap1[1];
            float4 bf0 = *(const float4*)&Bs[k][col0];
            float4 bf1 = *(const float4*)&Bs[k][col0 + 4];
            const float br[8] = {bf0.x,bf0.y,bf0.z,bf0.w,bf1.x,bf1.y,bf1.z,bf1.w};
#pragma unroll
            for (int j = 0; j < 8; j++) {
                const u64t bs = pack2(br[j], br[j]);
                ffma2(acc2[j][0], apair0, bs);
                ffma2(acc2[j][1], apair1, bs);
                ffma2(acc2[j][2], apair2, bs);
                ffma2(acc2[j][3], apair3, bs);
            }
        }
        if (more) {
            __syncthreads();
            As[lkc+0][lrow]=a0.x; As[lkc+1][lrow]=a0.y; As[lkc+2][lrow]=a0.z; As[lkc+3][lrow]=a0.w;
            As[lkc+4][lrow]=a1.x; As[lkc+5][lrow]=a1.y; As[lkc+6][lrow]=a1.z; As[lkc+7][lrow]=a1.w;
            Bs[lkc+0][lrow]=b0.x; Bs[lkc+1][lrow]=b0.y; Bs[lkc+2][lrow]=b0.z; Bs[lkc+3][lrow]=b0.w;
            Bs[lkc+4][lrow]=b1.x; Bs[lkc+5][lrow]=b1.y; Bs[lkc+6][lrow]=b1.z; Bs[lkc+7][lrow]=b1.w;
            __syncthreads();
        }
    }

    // unpack accumulators to acc[i][j]
    float acc[8][8];
#pragma unroll
    for (int j = 0; j < 8; j++)
#pragma unroll
        for (int p = 0; p < 4; p++)
            unpack2(acc2[j][p], acc[2*p][j], acc[2*p+1][j]);

    float4 bb0 = {0,0,0,0}, bb1 = {0,0,0,0};
    if (HASBIAS) {
        bb0 = *(const float4*)(bias + bn + col0);
        bb1 = *(const float4*)(bias + bn + col0 + 4);
    }
#pragma unroll
    for (int i = 0; i < 8; i++) {
        const int r = bm + row0 + i;
        float4 o0 = { acc[i][0] + bb0.x, acc[i][1] + bb0.y, acc[i][2] + bb0.z, acc[i][3] + bb0.w };
        float4 o1 = { acc[i][4] + bb1.x, acc[i][5] + bb1.y, acc[i][6] + bb1.z, acc[i][7] + bb1.w };
        if (RELU) {
            o0.x = fmaxf(o0.x, 0.f); o0.y = fmaxf(o0.y, 0.f); o0.z = fmaxf(o0.z, 0.f); o0.w = fmaxf(o0.w, 0.f);
            o1.x = fmaxf(o1.x, 0.f); o1.y = fmaxf(o1.y, 0.f); o1.z = fmaxf(o1.z, 0.f); o1.w = fmaxf(o1.w, 0.f);
        }
        *(float4*)(C + (size_t)r * ldc + bn + col0)     = o0;
        *(float4*)(C + (size_t)r * ldc + bn + col0 + 4) = o1;
    }
}

// ---------------- split-K combine for gemm1: g_h = relu(sum4 + b1) ----------------
__global__ void __launch_bounds__(256) combine_relu(const float* __restrict__ b1)
{
    const int i = blockIdx.x * 256 + threadIdx.x;      // float4 id, 131072 total
    const int c4 = (i & 63) << 2;
    const size_t off = (size_t)i;
    const float4* p = (const float4*)g_c1part;
    const size_t stride = (size_t)N_TOK * C1 / 4;
    float4 v0 = p[off], v1 = p[off + stride], v2 = p[off + 2*stride], v3 = p[off + 3*stride];
    float4 bb = *(const float4*)(b1 + c4);
    float4 o;
    o.x = fmaxf((v0.x + v1.x) + (v2.x + v3.x) + bb.x, 0.f);
    o.y = fmaxf((v0.y + v1.y) + (v2.y + v3.y) + bb.y, 0.f);
    o.z = fmaxf((v0.z + v1.z) + (v2.z + v3.z) + bb.z, 0.f);
    o.w = fmaxf((v0.w + v1.w) + (v2.w + v3.w) + bb.w, 0.f);
    ((float4*)g_h)[off] = o;
}

// ---------------- BN statistics: 256 blocks x 256 thr, float4 loads ----------------
__global__ void __launch_bounds__(256) bn_partial()
{
    const int b = blockIdx.x;          // 256 blocks, 32 rows each
    const int t = threadIdx.x;
    const int dq = t & 63;             // float4 column 0..63
    const int rg = t >> 6;             // 0..3 row subgroup
    const float4* base = (const float4*)g_q + ((size_t)b * 32 + rg * 8) * 64 + dq;
    float4 s = {0,0,0,0}, s2 = {0,0,0,0};
#pragma unroll
    for (int i = 0; i < 8; i++) {
        float4 v = base[(size_t)i * 64];
        s.x += v.x; s.y += v.y; s.z += v.z; s.w += v.w;
        s2.x += v.x * v.x; s2.y += v.y * v.y; s2.z += v.z * v.z; s2.w += v.w * v.w;
    }
    __shared__ float4 sh1[256], sh2[256];
    sh1[t] = s; sh2[t] = s2;
    __syncthreads();
    if (rg == 0) {
        float4 x1 = sh1[dq + 64], x2 = sh1[dq + 128], x3 = sh1[dq + 192];
        s.x += x1.x + x2.x + x3.x; s.y += x1.y + x2.y + x3.y;
        s.z += x1.z + x2.z + x3.z; s.w += x1.w + x2.w + x3.w;
        float4 y1 = sh2[dq + 64], y2 = sh2[dq + 128], y3 = sh2[dq + 192];
        s2.x += y1.x + y2.x + y3.x; s2.y += y1.y + y2.y + y3.y;
        s2.z += y1.z + y2.z + y3.z; s2.w += y1.w + y2.w + y3.w;
        const int d = dq << 2;
        g_bnpart[(size_t)(d + 0) * 256 + b] = s.x;
        g_bnpart[(size_t)(d + 1) * 256 + b] = s.y;
        g_bnpart[(size_t)(d + 2) * 256 + b] = s.z;
        g_bnpart[(size_t)(d + 3) * 256 + b] = s.w;
        g_bnpart[(size_t)(KDIM + d + 0) * 256 + b] = s2.x;
        g_bnpart[(size_t)(KDIM + d + 1) * 256 + b] = s2.y;
        g_bnpart[(size_t)(KDIM + d + 2) * 256 + b] = s2.z;
        g_bnpart[(size_t)(KDIM + d + 3) * 256 + b] = s2.w;
    }
}

__global__ void __launch_bounds__(256) bn_finalize(const float* __restrict__ gamma,
                                                   const float* __restrict__ beta)
{
    const int d = blockIdx.x, t = threadIdx.x;
    float s  = g_bnpart[(size_t)d * 256 + t];
    float s2 = g_bnpart[(size_t)(KDIM + d) * 256 + t];
#pragma unroll
    for (int o = 16; o > 0; o >>= 1) {
        s  += __shfl_xor_sync(0xffffffffu, s, o);
        s2 += __shfl_xor_sync(0xffffffffu, s2, o);
    }
    __shared__ float r1[8], r2[8];
    if ((t & 31) == 0) { r1[t >> 5] = s; r2[t >> 5] = s2; }
    __syncthreads();
    if (t == 0) {
        s  = ((r1[0] + r1[1]) + (r1[2] + r1[3])) + ((r1[4] + r1[5]) + (r1[6] + r1[7]));
        s2 = ((r2[0] + r2[1]) + (r2[2] + r2[3])) + ((r2[4] + r2[5]) + (r2[6] + r2[7]));
        const float inv = 1.0f / 8192.0f;
        float mean = s * inv;
        float var  = s2 * inv - mean * mean;
        float sc = rsqrtf(var + 1e-5f) * gamma[d];
        g_scale[d] = sc;
        g_shift[d] = beta[d] - mean * sc;
    }
}

// ---------------- two-level top-k + softmax ----------------
__global__ void __launch_bounds__(64) topk_kernel()
{
    const int b = blockIdx.x;
    const int t = b >> 2, h = b & 3;
    const int w = threadIdx.x >> 5;
    const int lane = threadIdx.x & 31;

    __shared__ float sts[2][32];
    __shared__ int   sti[2][32];
    __shared__ float cv[128];
    __shared__ int   ci[128];

    {
        const float* row = g_s + ((size_t)(h * 2 + w) * N_TOK + t) * SUBN;
        float v[16];
#pragma unroll
        for (int c = 0; c < 16; c++) v[c] = row[lane + 32 * c];
        float myv = 0.f; int myi = 0;
        for (int it = 0; it < 32; it++) {
            float lm = neg_inf(); int lc2 = 0;
#pragma unroll
            for (int c = 0; c < 16; c++) if (v[c] > lm) { lm = v[c]; lc2 = c; }
            float bv = lm; int bi = lane + 32 * lc2;
#pragma unroll
            for (int o = 16; o > 0; o >>= 1) {
                float ov = __shfl_xor_sync(0xffffffffu, bv, o);
                int   oi = __shfl_xor_sync(0xffffffffu, bi, o);
                if (ov > bv || (ov == bv && oi < bi)) { bv = ov; bi = oi; }
            }
            if (lane == it) { myv = bv; myi = bi; }
            if (lane == (bi & 31)) {
                int cc = bi >> 5;
#pragma unroll
                for (int c = 0; c < 16; c++) if (c == cc) v[c] = neg_inf();
            }
        }
        sts[w][lane] = myv; sti[w][lane] = myi;
    }
    __syncthreads();

    if (w == 0) {
#pragma unroll
        for (int c = 0; c < 4; c++) cv[lane + 32 * c] = neg_inf();
        __syncwarp();
        {
            const int jm = c_jm[lane], base = c_base[lane];
            const float a = sts[0][lane];
            const int  ia = sti[0][lane];
            for (int j = 0; j < jm; j++) {
                cv[base + j] = a + sts[1][j];
                ci[base + j] = ia * SUBN + sti[1][j];
            }
        }
        __syncwarp();
        float v[4];
#pragma unroll
        for (int c = 0; c < 4; c++) v[c] = cv[lane + 32 * c];
        float myv = 0.f; int mys = 0;
        for (int it = 0; it < 32; it++) {
            float lm = neg_inf(); int lc2 = 0;
#pragma unroll
            for (int c = 0; c < 4; c++) if (v[c] > lm) { lm = v[c]; lc2 = c; }
            float bv = lm; int bi = lane + 32 * lc2;
#pragma unroll
            for (int o = 16; o > 0; o >>= 1) {
                float ov = __shfl_xor_sync(0xffffffffu, bv, o);
                int   oi = __shfl_xor_sync(0xffffffffu, bi, o);
                if (ov > bv || (ov == bv && oi < bi)) { bv = ov; bi = oi; }
            }
            if (lane == it) { myv = bv; mys = bi; }
            if (lane == (bi & 31)) {
                int cc = bi >> 5;
#pragma unroll
                for (int c = 0; c < 4; c++) if (c == cc) v[c] = neg_inf();
            }
        }
        const float mx = __shfl_sync(0xffffffffu, myv, 0);
        float e = expf(myv - mx);
        float sum = e;
#pragma unroll
        for (int o = 16; o > 0; o >>= 1) sum += __shfl_xor_sync(0xffffffffu, sum, o);
        const size_t oo = (size_t)t * (HEADS * KNN) + h * KNN + lane;
        g_idx[oo] = ci[mys];
        g_w[oo]   = e / sum;
    }
}

// ---------------- weighted gather from values table (MLP=4) ----------------
__global__ void __launch_bounds__(128) gather_kernel(const float* __restrict__ values)
{
    const int t = blockIdx.x;
    const int tid = threadIdx.x;
    __shared__ int   sidx[128];
    __shared__ float sw[128];
    sidx[tid] = g_idx[(size_t)t * 128 + tid];
    sw[tid]   = g_w[(size_t)t * 128 + tid];
    __syncthreads();

    const int col = tid << 2;
    float4 a0 = {0,0,0,0}, a1 = {0,0,0,0}, a2 = {0,0,0,0}, a3 = {0,0,0,0};
#pragma unroll
    for (int k = 0; k < 128; k += 4) {
        const float4 v0 = *(const float4*)(values + (size_t)sidx[k + 0] * HDIM + col);
        const float4 v1 = *(const float4*)(values + (size_t)sidx[k + 1] * HDIM + col);
        const float4 v2 = *(const float4*)(values + (size_t)sidx[k + 2] * HDIM + col);
        const float4 v3 = *(const float4*)(values + (size_t)sidx[k + 3] * HDIM + col);
        const float w0 = sw[k + 0], w1 = sw[k + 1], w2 = sw[k + 2], w3 = sw[k + 3];
        a0.x += w0 * v0.x; a0.y += w0 * v0.y; a0.z += w0 * v0.z; a0.w += w0 * v0.w;
        a1.x += w1 * v1.x; a1.y += w1 * v1.y; a1.z += w1 * v1.z; a1.w += w1 * v1.w;
        a2.x += w2 * v2.x; a2.y += w2 * v2.y; a2.z += w2 * v2.z; a2.w += w2 * v2.w;
        a3.x += w3 * v3.x; a3.y += w3 * v3.y; a3.z += w3 * v3.z; a3.w += w3 * v3.w;
    }
    float4 acc;
    acc.x = (a0.x + a1.x) + (a2.x + a3.x);
    acc.y = (a0.y + a1.y) + (a2.y + a3.y);
    acc.z = (a0.z + a1.z) + (a2.z + a3.z);
    acc.w = (a0.w + a1.w) + (a2.w + a3.w);
    *(float4*)(g_partial + (size_t)t * HDIM + col) = acc;
}

// ---------------- deterministic reduce over sequence ----------------
__global__ void __launch_bounds__(512) reduce_kernel(float* __restrict__ out)
{
    const int e = blockIdx.x * 512 + threadIdx.x;   // 0..16383
    const int bb = e >> 9, c = e & 511;
    float s0 = 0.f, s1 = 0.f, s2 = 0.f, s3 = 0.f;
#pragma unroll
    for (int l = 0; l < 64; l += 4) {
        s0 += g_partial[(size_t)((bb << 6) + l + 0) * HDIM + c];
        s1 += g_partial[(size_t)((bb << 6) + l + 1) * HDIM + c];
        s2 += g_partial[(size_t)((bb << 6) + l + 2) * HDIM + c];
        s3 += g_partial[(size_t)((bb << 6) + l + 3) * HDIM + c];
    }
    out[e] = (s0 + s1) + (s2 + s3);
}

// ---------------- launch ----------------
extern "C" void kernel_launch(void* const* d_in, const int* in_sizes, int n_in,
                              void* d_out, int out_size)
{
    (void)in_sizes; (void)n_in; (void)out_size;
    const float* x        = (const float*)d_in[0];
    const float* w1       = (const float*)d_in[1];
    const float* b1       = (const float*)d_in[2];
    const float* w2       = (const float*)d_in[3];
    const float* b2       = (const float*)d_in[4];
    const float* bn_gamma = (const float*)d_in[5];
    const float* bn_beta  = (const float*)d_in[6];
    const float* keys     = (const float*)d_in[7];
    const float* values   = (const float*)d_in[8];
    float* out = (float*)d_out;

    float *d_h, *d_q, *d_c1, *d_s;
    cudaGetSymbolAddress((void**)&d_h, g_h);
    cudaGetSymbolAddress((void**)&d_q, g_q);
    cudaGetSymbolAddress((void**)&d_c1, g_c1part);
    cudaGetSymbolAddress((void**)&d_s, g_s);

    // 1) gemm1 split-K=4: partials [4][2048x256]
    sgemm128<128, HDIM, HDIM, false, false, false>
        <<<dim3(16, 2, 4), 256>>>(x, w1, nullptr, d_c1, C1, 128, 128, (size_t)N_TOK * C1);
    // 1b) combine + bias + relu -> g_h
    combine_relu<<<512, 256>>>(b1);
    // 2) q = h @ w2^T + b2   [2048 x 1024]
    sgemm128<C1, C1, C1, false, true, false>
        <<<dim3(16, 8, 1), 256>>>(d_h, w2, b2, d_q, D2, 0, 0, 0);
    // 3) BN stats
    bn_partial<<<256, 256>>>();
    bn_finalize<<<KDIM, 256>>>(bn_gamma, bn_beta);
    // 4) scores with fused BN normalize  [8][2048][512]
    sgemm128<HALFD, D2, HALFD, false, false, true>
        <<<dim3(16, 4, 8), 256>>>(d_q, keys, nullptr, d_s, SUBN,
                                  128, SUBN * HALFD, (size_t)N_TOK * SUBN);
    // 5) two-level top-k + softmax
    topk_kernel<<<N_TOK * HEADS, 64>>>();
    // 6) weighted gather
    gather_kernel<<<N_TOK, 128>>>(values);
    // 7) sum over sequence
    reduce_kernel<<<32, 512>>>(out);
}

// round 5
// speedup vs baseline: 1.3261x; 1.1829x over previous
#include <cuda_runtime.h>
#include <math.h>

#define N_TOK 2048
#define HDIM  512
#define C1    256
#define D2    1024
#define KDIM  256
#define HALFD 128
#define HEADS 4
#define SUBN  512
#define KNN   32

// ---------------- static device scratch (no allocations allowed) ----------------
__device__ float g_h[N_TOK * C1];                 // 2 MB
__device__ float g_c1part[4 * N_TOK * C1];        // 8 MB split-K partials for gemm1
__device__ float g_q[N_TOK * D2];                 // 8 MB
__device__ float g_bnpart[2 * KDIM * 256];        // [stat][d][block]
__device__ float g_scale[KDIM];
__device__ float g_shift[KDIM];
__device__ float g_s[8u * N_TOK * SUBN];          // 32 MB scores [z][t][k]
__device__ int   g_idx[N_TOK * HEADS * KNN];
__device__ float g_w[N_TOK * HEADS * KNN];
__device__ float g_partial[N_TOK * HDIM];         // per-token gather result

// phase-2 slot table: 119 pruned pairs (i+1)*(j+1)<=32, packed (i<<8)|j
__constant__ unsigned short c_pp[128] = {
    // i=0, j=0..31
    0x000,0x001,0x002,0x003,0x004,0x005,0x006,0x007,
    0x008,0x009,0x00A,0x00B,0x00C,0x00D,0x00E,0x00F,
    0x010,0x011,0x012,0x013,0x014,0x015,0x016,0x017,
    0x018,0x019,0x01A,0x01B,0x01C,0x01D,0x01E,0x01F,
    // i=1, j=0..15
    0x100,0x101,0x102,0x103,0x104,0x105,0x106,0x107,
    0x108,0x109,0x10A,0x10B,0x10C,0x10D,0x10E,0x10F,
    // i=2, j=0..9
    0x200,0x201,0x202,0x203,0x204,0x205,0x206,0x207,0x208,0x209,
    // i=3, j=0..7
    0x300,0x301,0x302,0x303,0x304,0x305,0x306,0x307,
    // i=4, j=0..5
    0x400,0x401,0x402,0x403,0x404,0x405,
    // i=5, j=0..4
    0x500,0x501,0x502,0x503,0x504,
    // i=6, j=0..3
    0x600,0x601,0x602,0x603,
    // i=7, j=0..3
    0x700,0x701,0x702,0x703,
    // i=8, j=0..2
    0x800,0x801,0x802,
    // i=9, j=0..2
    0x900,0x901,0x902,
    // i=10..15, j=0..1
    0xA00,0xA01,0xB00,0xB01,0xC00,0xC01,0xD00,0xD01,0xE00,0xE01,0xF00,0xF01,
    // i=16..31, j=0
    0x1000,0x1100,0x1200,0x1300,0x1400,0x1500,0x1600,0x1700,
    0x1800,0x1900,0x1A00,0x1B00,0x1C00,0x1D00,0x1E00,0x1F00,
    // sentinels 119..127
    0,0,0,0,0,0,0,0,0
};

// order-preserving float<->uint transform (uint compare == float compare)
__device__ __forceinline__ unsigned int ordu(float f) {
    int s = __float_as_int(f);
    return (unsigned int)(s ^ ((s >> 31) | 0x80000000));
}
__device__ __forceinline__ float unordu(unsigned int u) {
    int s = (u & 0x80000000u) ? (int)(u ^ 0x80000000u) : (int)~u;
    return __int_as_float(s);
}

// =====================================================================================
// 128x128 tile SGEMM, 256 threads, 8x8 microtile, BK=16 (scalar FFMA - best measured).
// =====================================================================================
template<int K, int LDA, int LDB, bool RELU, bool HASBIAS, bool NORM>
__global__ void __launch_bounds__(256) sgemm128(const float* __restrict__ A,
                                                const float* __restrict__ B,
                                                const float* __restrict__ bias,
                                                float* __restrict__ C,
                                                int ldc, int aZ, int bZ, size_t cZ)
{
    __shared__ float As[16][132];
    __shared__ float Bs[16][132];
    const int tid = threadIdx.x;
    const int z = blockIdx.z;
    const int bm = blockIdx.x * 128, bn = blockIdx.y * 128;
    A += (size_t)z * aZ;
    B += (size_t)z * bZ;
    C += (size_t)z * cZ;

    const int lrow = tid >> 1;               // 0..127
    const int lkc  = (tid & 1) << 3;         // 0 or 8
    const float* Aptr = A + (size_t)(bm + lrow) * LDA + lkc;
    const float* Bptr = B + (size_t)(bn + lrow) * LDB + lkc;

    const int w = tid >> 5, lane = tid & 31;
    const int row0 = ((w & 1) << 6) + ((lane & 7) << 3);   // 0..120
    const int col0 = ((w >> 1) << 5) + ((lane >> 3) << 3); // 0..120

    float acc[8][8] = {};
    float4 a0, a1, b0, b1;

    a0 = *(const float4*)(Aptr);     a1 = *(const float4*)(Aptr + 4);
    b0 = *(const float4*)(Bptr);     b1 = *(const float4*)(Bptr + 4);
    if (NORM) {
        const int dk = ((z & 1) << 7) + lkc;
        float4 sc0 = *(const float4*)(g_scale + dk), sh0 = *(const float4*)(g_shift + dk);
        float4 sc1 = *(const float4*)(g_scale + dk + 4), sh1 = *(const float4*)(g_shift + dk + 4);
        a0.x = fmaf(a0.x, sc0.x, sh0.x); a0.y = fmaf(a0.y, sc0.y, sh0.y);
        a0.z = fmaf(a0.z, sc0.z, sh0.z); a0.w = fmaf(a0.w, sc0.w, sh0.w);
        a1.x = fmaf(a1.x, sc1.x, sh1.x); a1.y = fmaf(a1.y, sc1.y, sh1.y);
        a1.z = fmaf(a1.z, sc1.z, sh1.z); a1.w = fmaf(a1.w, sc1.w, sh1.w);
    }
    As[lkc+0][lrow]=a0.x; As[lkc+1][lrow]=a0.y; As[lkc+2][lrow]=a0.z; As[lkc+3][lrow]=a0.w;
    As[lkc+4][lrow]=a1.x; As[lkc+5][lrow]=a1.y; As[lkc+6][lrow]=a1.z; As[lkc+7][lrow]=a1.w;
    Bs[lkc+0][lrow]=b0.x; Bs[lkc+1][lrow]=b0.y; Bs[lkc+2][lrow]=b0.z; Bs[lkc+3][lrow]=b0.w;
    Bs[lkc+4][lrow]=b1.x; Bs[lkc+5][lrow]=b1.y; Bs[lkc+6][lrow]=b1.z; Bs[lkc+7][lrow]=b1.w;
    __syncthreads();

#pragma unroll 1
    for (int kb = 1; kb <= K / 16; kb++) {
        const bool more = kb < K / 16;
        if (more) {
            const int k0 = kb * 16;
            a0 = *(const float4*)(Aptr + k0);     a1 = *(const float4*)(Aptr + k0 + 4);
            b0 = *(const float4*)(Bptr + k0);     b1 = *(const float4*)(Bptr + k0 + 4);
            if (NORM) {
                const int dk = ((z & 1) << 7) + lkc + k0;
                float4 sc0 = *(const float4*)(g_scale + dk), sh0 = *(const float4*)(g_shift + dk);
                float4 sc1 = *(const float4*)(g_scale + dk + 4), sh1 = *(const float4*)(g_shift + dk + 4);
                a0.x = fmaf(a0.x, sc0.x, sh0.x); a0.y = fmaf(a0.y, sc0.y, sh0.y);
                a0.z = fmaf(a0.z, sc0.z, sh0.z); a0.w = fmaf(a0.w, sc0.w, sh0.w);
                a1.x = fmaf(a1.x, sc1.x, sh1.x); a1.y = fmaf(a1.y, sc1.y, sh1.y);
                a1.z = fmaf(a1.z, sc1.z, sh1.z); a1.w = fmaf(a1.w, sc1.w, sh1.w);
            }
        }
#pragma unroll
        for (int k = 0; k < 16; k++) {
            float4 af0 = *(const float4*)&As[k][row0];
            float4 af1 = *(const float4*)&As[k][row0 + 4];
            float4 bf0 = *(const float4*)&Bs[k][col0];
            float4 bf1 = *(const float4*)&Bs[k][col0 + 4];
            const float ar[8] = {af0.x,af0.y,af0.z,af0.w,af1.x,af1.y,af1.z,af1.w};
            const float br[8] = {bf0.x,bf0.y,bf0.z,bf0.w,bf1.x,bf1.y,bf1.z,bf1.w};
#pragma unroll
            for (int i = 0; i < 8; i++)
#pragma unroll
                for (int j = 0; j < 8; j++)
                    acc[i][j] = fmaf(ar[i], br[j], acc[i][j]);
        }
        if (more) {
            __syncthreads();
            As[lkc+0][lrow]=a0.x; As[lkc+1][lrow]=a0.y; As[lkc+2][lrow]=a0.z; As[lkc+3][lrow]=a0.w;
            As[lkc+4][lrow]=a1.x; As[lkc+5][lrow]=a1.y; As[lkc+6][lrow]=a1.z; As[lkc+7][lrow]=a1.w;
            Bs[lkc+0][lrow]=b0.x; Bs[lkc+1][lrow]=b0.y; Bs[lkc+2][lrow]=b0.z; Bs[lkc+3][lrow]=b0.w;
            Bs[lkc+4][lrow]=b1.x; Bs[lkc+5][lrow]=b1.y; Bs[lkc+6][lrow]=b1.z; Bs[lkc+7][lrow]=b1.w;
            __syncthreads();
        }
    }

    float4 bb0 = {0,0,0,0}, bb1 = {0,0,0,0};
    if (HASBIAS) {
        bb0 = *(const float4*)(bias + bn + col0);
        bb1 = *(const float4*)(bias + bn + col0 + 4);
    }
#pragma unroll
    for (int i = 0; i < 8; i++) {
        const int r = bm + row0 + i;
        float4 o0 = { acc[i][0] + bb0.x, acc[i][1] + bb0.y, acc[i][2] + bb0.z, acc[i][3] + bb0.w };
        float4 o1 = { acc[i][4] + bb1.x, acc[i][5] + bb1.y, acc[i][6] + bb1.z, acc[i][7] + bb1.w };
        if (RELU) {
            o0.x = fmaxf(o0.x, 0.f); o0.y = fmaxf(o0.y, 0.f); o0.z = fmaxf(o0.z, 0.f); o0.w = fmaxf(o0.w, 0.f);
            o1.x = fmaxf(o1.x, 0.f); o1.y = fmaxf(o1.y, 0.f); o1.z = fmaxf(o1.z, 0.f); o1.w = fmaxf(o1.w, 0.f);
        }
        *(float4*)(C + (size_t)r * ldc + bn + col0)     = o0;
        *(float4*)(C + (size_t)r * ldc + bn + col0 + 4) = o1;
    }
}

// ---------------- split-K combine for gemm1 ----------------
__global__ void __launch_bounds__(256) combine_relu(const float* __restrict__ b1)
{
    const int i = blockIdx.x * 256 + threadIdx.x;
    const int c4 = (i & 63) << 2;
    const size_t off = (size_t)i;
    const float4* p = (const float4*)g_c1part;
    const size_t stride = (size_t)N_TOK * C1 / 4;
    float4 v0 = p[off], v1 = p[off + stride], v2 = p[off + 2*stride], v3 = p[off + 3*stride];
    float4 bb = *(const float4*)(b1 + c4);
    float4 o;
    o.x = fmaxf((v0.x + v1.x) + (v2.x + v3.x) + bb.x, 0.f);
    o.y = fmaxf((v0.y + v1.y) + (v2.y + v3.y) + bb.y, 0.f);
    o.z = fmaxf((v0.z + v1.z) + (v2.z + v3.z) + bb.z, 0.f);
    o.w = fmaxf((v0.w + v1.w) + (v2.w + v3.w) + bb.w, 0.f);
    ((float4*)g_h)[off] = o;
}

// ---------------- BN statistics ----------------
__global__ void __launch_bounds__(256) bn_partial()
{
    const int b = blockIdx.x;
    const int t = threadIdx.x;
    const int dq = t & 63;
    const int rg = t >> 6;
    const float4* base = (const float4*)g_q + ((size_t)b * 32 + rg * 8) * 64 + dq;
    float4 s = {0,0,0,0}, s2 = {0,0,0,0};
#pragma unroll
    for (int i = 0; i < 8; i++) {
        float4 v = base[(size_t)i * 64];
        s.x += v.x; s.y += v.y; s.z += v.z; s.w += v.w;
        s2.x += v.x * v.x; s2.y += v.y * v.y; s2.z += v.z * v.z; s2.w += v.w * v.w;
    }
    __shared__ float4 sh1[256], sh2[256];
    sh1[t] = s; sh2[t] = s2;
    __syncthreads();
    if (rg == 0) {
        float4 x1 = sh1[dq + 64], x2 = sh1[dq + 128], x3 = sh1[dq + 192];
        s.x += x1.x + x2.x + x3.x; s.y += x1.y + x2.y + x3.y;
        s.z += x1.z + x2.z + x3.z; s.w += x1.w + x2.w + x3.w;
        float4 y1 = sh2[dq + 64], y2 = sh2[dq + 128], y3 = sh2[dq + 192];
        s2.x += y1.x + y2.x + y3.x; s2.y += y1.y + y2.y + y3.y;
        s2.z += y1.z + y2.z + y3.z; s2.w += y1.w + y2.w + y3.w;
        const int d = dq << 2;
        g_bnpart[(size_t)(d + 0) * 256 + b] = s.x;
        g_bnpart[(size_t)(d + 1) * 256 + b] = s.y;
        g_bnpart[(size_t)(d + 2) * 256 + b] = s.z;
        g_bnpart[(size_t)(d + 3) * 256 + b] = s.w;
        g_bnpart[(size_t)(KDIM + d + 0) * 256 + b] = s2.x;
        g_bnpart[(size_t)(KDIM + d + 1) * 256 + b] = s2.y;
        g_bnpart[(size_t)(KDIM + d + 2) * 256 + b] = s2.z;
        g_bnpart[(size_t)(KDIM + d + 3) * 256 + b] = s2.w;
    }
}

__global__ void __launch_bounds__(256) bn_finalize(const float* __restrict__ gamma,
                                                   const float* __restrict__ beta)
{
    const int d = blockIdx.x, t = threadIdx.x;
    float s  = g_bnpart[(size_t)d * 256 + t];
    float s2 = g_bnpart[(size_t)(KDIM + d) * 256 + t];
#pragma unroll
    for (int o = 16; o > 0; o >>= 1) {
        s  += __shfl_xor_sync(0xffffffffu, s, o);
        s2 += __shfl_xor_sync(0xffffffffu, s2, o);
    }
    __shared__ float r1[8], r2[8];
    if ((t & 31) == 0) { r1[t >> 5] = s; r2[t >> 5] = s2; }
    __syncthreads();
    if (t == 0) {
        s  = ((r1[0] + r1[1]) + (r1[2] + r1[3])) + ((r1[4] + r1[5]) + (r1[6] + r1[7]));
        s2 = ((r2[0] + r2[1]) + (r2[2] + r2[3])) + ((r2[4] + r2[5]) + (r2[6] + r2[7]));
        const float inv = 1.0f / 8192.0f;
        float mean = s * inv;
        float var  = s2 * inv - mean * mean;
        float sc = rsqrtf(var + 1e-5f) * gamma[d];
        g_scale[d] = sc;
        g_shift[d] = beta[d] - mean * sc;
    }
}

// ---------------- two-level top-k + softmax (REDUX-based tournament) ----------------
__global__ void __launch_bounds__(64) topk_kernel()
{
    const int b = blockIdx.x;
    const int t = b >> 2, h = b & 3;
    const int w = threadIdx.x >> 5;          // half index (warp)
    const int lane = threadIdx.x & 31;

    __shared__ float sts[2][32];   // sorted top-32 values (descending)
    __shared__ int   sti[2][32];   // original indices in [0,512)

    // ---- phase 1: each warp extracts sorted top-32 of its 512-score row ----
    {
        const float* row = g_s + ((size_t)(h * 2 + w) * N_TOK + t) * SUBN;
        unsigned int v[16];
#pragma unroll
        for (int c = 0; c < 16; c++) v[c] = ordu(row[lane + 32 * c]);

        for (int it = 0; it < 32; it++) {
            // local max with smallest c (ascending c == ascending global idx)
            unsigned int lm = v[0]; int lc = 0;
#pragma unroll
            for (int c = 1; c < 16; c++) if (v[c] > lm) { lm = v[c]; lc = c; }
            const unsigned int wm = __reduce_max_sync(0xffffffffu, lm);
            const unsigned int myidx = (lm == wm) ? (unsigned int)(lane + (lc << 5)) : 0xffffffffu;
            const unsigned int wi = __reduce_min_sync(0xffffffffu, myidx);
            if (lane == it) { sts[w][it] = unordu(wm); sti[w][it] = (int)wi; }
            if (lane == (int)(wi & 31)) {
                const int cc = (int)(wi >> 5);
#pragma unroll
                for (int c = 0; c < 16; c++) if (c == cc) v[c] = 0u;
            }
        }
    }
    __syncthreads();

    // ---- phase 2: warp 0 — 119 pruned pair sums, top-32, softmax ----
    if (w == 0) {
        unsigned int key[4];
        unsigned int flt[4];
#pragma unroll
        for (int q = 0; q < 4; q++) {
            const int s = lane + (q << 5);
            const int pp = c_pp[s];
            const int i = pp >> 8, j = pp & 0xff;
            const float sum = sts[0][i] + sts[1][j];
            key[q] = (s < 119) ? ordu(sum) : 0u;
            flt[q] = (unsigned int)((i << 5) | j);     // flat index in 32x32 grid
        }

        unsigned int selu = 0, self = 0;
        for (int it = 0; it < 32; it++) {
            unsigned int lm = key[0], lf = flt[0]; int lq = 0;
#pragma unroll
            for (int q = 1; q < 4; q++) {
                if (key[q] > lm || (key[q] == lm && flt[q] < lf)) { lm = key[q]; lf = flt[q]; lq = q; }
            }
            const unsigned int wm = __reduce_max_sync(0xffffffffu, lm);
            const unsigned int mf = (lm == wm) ? lf : 0xffffffffu;
            const unsigned int wf = __reduce_min_sync(0xffffffffu, mf);
            if (lane == it) { selu = wm; self = wf; }
            if (lm == wm && lf == wf) {      // unique owner invalidates its slot
#pragma unroll
                for (int q = 0; q < 4; q++) if (q == lq) key[q] = 0u;
            }
        }

        const float myv = unordu(selu);
        const int i = (int)(self >> 5), j = (int)(self & 31);
        const int idx = sti[0][i] * SUBN + sti[1][j];

        const float mx = __shfl_sync(0xffffffffu, myv, 0);   // lane 0 holds the max
        float e = expf(myv - mx);
        float sum = e;
#pragma unroll
        for (int o = 16; o > 0; o >>= 1) sum += __shfl_xor_sync(0xffffffffu, sum, o);
        const size_t oo = (size_t)t * (HEADS * KNN) + h * KNN + lane;
        g_idx[oo] = idx;
        g_w[oo]   = e / sum;
    }
}

// ---------------- weighted gather from values table (MLP=4) ----------------
__global__ void __launch_bounds__(128) gather_kernel(const float* __restrict__ values)
{
    const int t = blockIdx.x;
    const int tid = threadIdx.x;
    __shared__ int   sidx[128];
    __shared__ float sw[128];
    sidx[tid] = g_idx[(size_t)t * 128 + tid];
    sw[tid]   = g_w[(size_t)t * 128 + tid];
    __syncthreads();

    const int col = tid << 2;
    float4 a0 = {0,0,0,0}, a1 = {0,0,0,0}, a2 = {0,0,0,0}, a3 = {0,0,0,0};
#pragma unroll
    for (int k = 0; k < 128; k += 4) {
        const float4 v0 = *(const float4*)(values + (size_t)sidx[k + 0] * HDIM + col);
        const float4 v1 = *(const float4*)(values + (size_t)sidx[k + 1] * HDIM + col);
        const float4 v2 = *(const float4*)(values + (size_t)sidx[k + 2] * HDIM + col);
        const float4 v3 = *(const float4*)(values + (size_t)sidx[k + 3] * HDIM + col);
        const float w0 = sw[k + 0], w1 = sw[k + 1], w2 = sw[k + 2], w3 = sw[k + 3];
        a0.x += w0 * v0.x; a0.y += w0 * v0.y; a0.z += w0 * v0.z; a0.w += w0 * v0.w;
        a1.x += w1 * v1.x; a1.y += w1 * v1.y; a1.z += w1 * v1.z; a1.w += w1 * v1.w;
        a2.x += w2 * v2.x; a2.y += w2 * v2.y; a2.z += w2 * v2.z; a2.w += w2 * v2.w;
        a3.x += w3 * v3.x; a3.y += w3 * v3.y; a3.z += w3 * v3.z; a3.w += w3 * v3.w;
    }
    float4 acc;
    acc.x = (a0.x + a1.x) + (a2.x + a3.x);
    acc.y = (a0.y + a1.y) + (a2.y + a3.y);
    acc.z = (a0.z + a1.z) + (a2.z + a3.z);
    acc.w = (a0.w + a1.w) + (a2.w + a3.w);
    *(float4*)(g_partial + (size_t)t * HDIM + col) = acc;
}

// ---------------- deterministic reduce over sequence ----------------
__global__ void __launch_bounds__(512) reduce_kernel(float* __restrict__ out)
{
    const int e = blockIdx.x * 512 + threadIdx.x;
    const int bb = e >> 9, c = e & 511;
    float s0 = 0.f, s1 = 0.f, s2 = 0.f, s3 = 0.f;
#pragma unroll
    for (int l = 0; l < 64; l += 4) {
        s0 += g_partial[(size_t)((bb << 6) + l + 0) * HDIM + c];
        s1 += g_partial[(size_t)((bb << 6) + l + 1) * HDIM + c];
        s2 += g_partial[(size_t)((bb << 6) + l + 2) * HDIM + c];
        s3 += g_partial[(size_t)((bb << 6) + l + 3) * HDIM + c];
    }
    out[e] = (s0 + s1) + (s2 + s3);
}

// ---------------- launch ----------------
extern "C" void kernel_launch(void* const* d_in, const int* in_sizes, int n_in,
                              void* d_out, int out_size)
{
    (void)in_sizes; (void)n_in; (void)out_size;
    const float* x        = (const float*)d_in[0];
    const float* w1       = (const float*)d_in[1];
    const float* b1       = (const float*)d_in[2];
    const float* w2       = (const float*)d_in[3];
    const float* b2       = (const float*)d_in[4];
    const float* bn_gamma = (const float*)d_in[5];
    const float* bn_beta  = (const float*)d_in[6];
    const float* keys     = (const float*)d_in[7];
    const float* values   = (const float*)d_in[8];
    float* out = (float*)d_out;

    float *d_h, *d_q, *d_c1, *d_s;
    cudaGetSymbolAddress((void**)&d_h, g_h);
    cudaGetSymbolAddress((void**)&d_q, g_q);
    cudaGetSymbolAddress((void**)&d_c1, g_c1part);
    cudaGetSymbolAddress((void**)&d_s, g_s);

    // 1) gemm1 split-K=4: partials [4][2048x256]
    sgemm128<128, HDIM, HDIM, false, false, false>
        <<<dim3(16, 2, 4), 256>>>(x, w1, nullptr, d_c1, C1, 128, 128, (size_t)N_TOK * C1);
    // 1b) combine + bias + relu -> g_h
    combine_relu<<<512, 256>>>(b1);
    // 2) q = h @ w2^T + b2   [2048 x 1024]
    sgemm128<C1, C1, C1, false, true, false>
        <<<dim3(16, 8, 1), 256>>>(d_h, w2, b2, d_q, D2, 0, 0, 0);
    // 3) BN stats
    bn_partial<<<256, 256>>>();
    bn_finalize<<<KDIM, 256>>>(bn_gamma, bn_beta);
    // 4) scores with fused BN normalize  [8][2048][512]
    sgemm128<HALFD, D2, HALFD, false, false, true>
        <<<dim3(16, 4, 8), 256>>>(d_q, keys, nullptr, d_s, SUBN,
                                  128, SUBN * HALFD, (size_t)N_TOK * SUBN);
    // 5) two-level top-k + softmax
    topk_kernel<<<N_TOK * HEADS, 64>>>();
    // 6) weighted gather
    gather_kernel<<<N_TOK, 128>>>(values);
    // 7) sum over sequence
    reduce_kernel<<<32, 512>>>(out);
}